// round 8
// baseline (speedup 1.0000x reference)
#include <cuda_runtime.h>
#include <cuda_fp16.h>
#include <cstdint>

// ---------------------------------------------------------------------------
// Problem constants
// ---------------------------------------------------------------------------
#define BATCH   4
#define SEQ     4096
#define HIDDEN  1024
#define MTOT    (BATCH * SEQ)          // 16384
#define NTOT    (3 * HIDDEN)           // 3072 (S | out1 | out2)

// GEMM tiling: CTA 128x256, 8 warps of 64x64, BK=64, single-pass fp16
#define BM 128
#define BN 256
#define BK 64                           // 64 fp16 = 128 B row (SW128 swizzle)
#define NKT (HIDDEN / BK)               // 16 k-tiles

#define A_BYTES 16384                   // 128 x 64 fp16
#define B_BYTES 32768                   // 256 x 64 fp16
#define STAGE_BYTES (A_BYTES + B_BYTES) // 48 KB
#define NSTAGE 3
#define SMEM_TOTAL (NSTAGE * STAGE_BYTES)    // 144 KB (Blackwell: up to ~227 KB)

// Scan tiling: 32-row chunks
#define NCH   128
#define CHUNK 32

// ---------------------------------------------------------------------------
// Scratch (static device memory only; no allocations allowed)
// ---------------------------------------------------------------------------
__device__ __align__(256) __half         g_Yh[(size_t)MTOT * NTOT];       // 96 MB
__device__ __align__(256) unsigned short g_Xh[(size_t)MTOT * HIDDEN];     // 32 MB
__device__ __align__(256) unsigned short g_Wh[(size_t)NTOT * HIDDEN];     // 6 MB
__device__ __align__(256) float          g_cmax[(size_t)BATCH * HIDDEN * NCH]; // 2 MB

// ---------------------------------------------------------------------------
// Small helpers
// ---------------------------------------------------------------------------
__device__ __forceinline__ uint32_t smem_to_u32(const void* smem_ptr) {
    uint32_t addr;
    asm("{ .reg .u64 tmp; cvta.to.shared.u64 tmp, %1; cvt.u32.u64 %0, tmp; }"
        : "=r"(addr) : "l"(smem_ptr));
    return addr;
}

__device__ __forceinline__ void cp_async16(uint32_t saddr, const void* gaddr) {
    asm volatile("cp.async.cg.shared.global [%0], [%1], 16;"
                 :: "r"(saddr), "l"(gaddr));
}
__device__ __forceinline__ void cp_commit() {
    asm volatile("cp.async.commit_group;");
}
template <int N>
__device__ __forceinline__ void cp_wait() {
    asm volatile("cp.async.wait_group %0;" :: "n"(N));
}

__device__ __forceinline__ void ldmatrix_x4(uint32_t& r0, uint32_t& r1,
                                            uint32_t& r2, uint32_t& r3,
                                            uint32_t addr) {
    asm volatile("ldmatrix.sync.aligned.m8n8.x4.shared.b16 {%0,%1,%2,%3}, [%4];"
                 : "=r"(r0), "=r"(r1), "=r"(r2), "=r"(r3) : "r"(addr));
}

__device__ __forceinline__ void mma_f16(float* d, const uint32_t* a,
                                        const uint32_t* b) {
    asm volatile(
        "mma.sync.aligned.m16n8k16.row.col.f32.f16.f16.f32 "
        "{%0,%1,%2,%3}, {%4,%5,%6,%7}, {%8,%9}, {%0,%1,%2,%3};"
        : "+f"(d[0]), "+f"(d[1]), "+f"(d[2]), "+f"(d[3])
        : "r"(a[0]), "r"(a[1]), "r"(a[2]), "r"(a[3]), "r"(b[0]), "r"(b[1]));
}

#define NEG_INF __int_as_float(0xff800000)

// ---------------------------------------------------------------------------
// Prep kernels: fp16 of X; fp16 of Wcat = [(W0+W1)/8 ; W1 ; W2]
// ---------------------------------------------------------------------------
__global__ __launch_bounds__(256) void prep_x_kernel(const float* __restrict__ X) {
    size_t i = (size_t)blockIdx.x * blockDim.x + threadIdx.x;   // vec4 index
    float4 v = reinterpret_cast<const float4*>(X)[i];
    ushort4 h;
    h.x = __half_as_ushort(__float2half_rn(v.x));
    h.y = __half_as_ushort(__float2half_rn(v.y));
    h.z = __half_as_ushort(__float2half_rn(v.z));
    h.w = __half_as_ushort(__float2half_rn(v.w));
    reinterpret_cast<ushort4*>(g_Xh)[i] = h;
}

__global__ __launch_bounds__(256) void prep_w_kernel(const float* __restrict__ W0,
                                                     const float* __restrict__ W1,
                                                     const float* __restrict__ W2) {
    size_t i = (size_t)blockIdx.x * blockDim.x + threadIdx.x;   // vec4 index
    size_t e = i * 4;
    int n = (int)(e >> 10);
    float4 w;
    if (n < HIDDEN) {
        float4 a = *reinterpret_cast<const float4*>(W0 + e);
        float4 b = *reinterpret_cast<const float4*>(W1 + e);
        w = make_float4((a.x + b.x) * 0.125f, (a.y + b.y) * 0.125f,
                        (a.z + b.z) * 0.125f, (a.w + b.w) * 0.125f);
    } else if (n < 2 * HIDDEN) {
        w = *reinterpret_cast<const float4*>(W1 + (e - (size_t)HIDDEN * HIDDEN));
    } else {
        w = *reinterpret_cast<const float4*>(W2 + (e - (size_t)2 * HIDDEN * HIDDEN));
    }
    ushort4 h;
    h.x = __half_as_ushort(__float2half_rn(w.x));
    h.y = __half_as_ushort(__float2half_rn(w.y));
    h.z = __half_as_ushort(__float2half_rn(w.z));
    h.w = __half_as_ushort(__float2half_rn(w.w));
    reinterpret_cast<ushort4*>(g_Wh)[i] = h;
}

// ---------------------------------------------------------------------------
// GEMM: Yh[16384,3072] = fp16( Xh@Wh^T ); fused per-chunk max of S columns.
// CTA 128x256, 8 warps of 64x64. 3-stage cp.async pipeline, 1 CTA/SM.
// ---------------------------------------------------------------------------
__device__ __forceinline__ void load_stage(uint32_t sbuf, int kt,
                                           int m0, int n0, int tid) {
    const int k0 = kt << 6;
    // A: 128 rows x 8 chunks = 1024
#pragma unroll
    for (int i = 0; i < 4; i++) {
        int id  = tid + i * 256;
        int row = id >> 3;
        int c   = id & 7;
        uint32_t off = (uint32_t)(row << 7) | (uint32_t)((c ^ (row & 7)) << 4);
        cp_async16(sbuf + off,
                   g_Xh + ((size_t)(m0 + row) << 10) + k0 + c * 8);
    }
    // B: 256 rows x 8 chunks = 2048
#pragma unroll
    for (int i = 0; i < 8; i++) {
        int id  = tid + i * 256;
        int row = id >> 3;
        int c   = id & 7;
        uint32_t off = (uint32_t)(row << 7) | (uint32_t)((c ^ (row & 7)) << 4);
        cp_async16(sbuf + A_BYTES + off,
                   g_Wh + ((size_t)(n0 + row) << 10) + k0 + c * 8);
    }
    cp_commit();
}

__global__ __launch_bounds__(256, 1) void gemm_kernel() {
    extern __shared__ char smem[];
    const uint32_t smem_base = smem_to_u32(smem);
    const int tid = threadIdx.x;
    const int wid = tid >> 5;
    const int lid = tid & 31;
    const int n0 = blockIdx.x * BN;
    const int m0 = blockIdx.y * BM;

    // Warp layout: 2 (m) x 4 (n); warp tile 64 x 64
    const int wm = (wid & 1) * 64;
    const int wn = (wid >> 1) * 64;

    // ldmatrix lane geometry
    const int lrow = (lid & 7) + ((lid >> 3) & 1) * 8;   // row within 16-row tile
    const int lchk = (lid >> 4);                          // 0/1: k 16B chunk

    float acc[4][8][4];
#pragma unroll
    for (int mt = 0; mt < 4; mt++)
#pragma unroll
        for (int nt = 0; nt < 8; nt++)
#pragma unroll
            for (int j = 0; j < 4; j++) acc[mt][nt][j] = 0.0f;

    load_stage(smem_base, 0, m0, n0, tid);
    load_stage(smem_base + STAGE_BYTES, 1, m0, n0, tid);

#pragma unroll 1
    for (int kt = 0; kt < NKT; kt++) {
        if (kt == NKT - 1) cp_wait<0>();
        else               cp_wait<1>();
        __syncthreads();
        // Prefetch kt+2: its buffer was last read in iteration kt-1, which
        // every warp finished before the barrier above.
        if (kt + 2 < NKT) {
            uint32_t sb = smem_base + ((kt + 2) % NSTAGE) * STAGE_BYTES;
            load_stage(sb, kt + 2, m0, n0, tid);
        }

        const uint32_t sA = smem_base + (kt % NSTAGE) * STAGE_BYTES;
        const uint32_t sB = sA + A_BYTES;

#pragma unroll
        for (int s = 0; s < 4; s++) {        // 4 sub-steps of k16
            const int chunk = 2 * s + lchk;
            // A fragments: 4 m-tiles of 16 rows
            uint32_t a[4][4];
#pragma unroll
            for (int mt = 0; mt < 4; mt++) {
                int row = wm + mt * 16 + lrow;
                uint32_t addr = sA + (uint32_t)(row << 7)
                              + (uint32_t)((chunk ^ (row & 7)) << 4);
                ldmatrix_x4(a[mt][0], a[mt][1], a[mt][2], a[mt][3], addr);
            }
            // B: 8 n-tiles of 8 rows, loaded pairwise (4 x ldmatrix.x4)
#pragma unroll
            for (int np = 0; np < 4; np++) {
                int row = wn + np * 16 + lrow;
                uint32_t addr = sB + (uint32_t)(row << 7)
                              + (uint32_t)((chunk ^ (row & 7)) << 4);
                uint32_t r0, r1, r2, r3;
                ldmatrix_x4(r0, r1, r2, r3, addr);
                uint32_t b0[2] = {r0, r2};   // n rows 0-7 of pair
                uint32_t b1[2] = {r1, r3};   // n rows 8-15 of pair
#pragma unroll
                for (int mt = 0; mt < 4; mt++) {
                    mma_f16(acc[mt][2 * np],     a[mt], b0);
                    mma_f16(acc[mt][2 * np + 1], a[mt], b1);
                }
            }
        }
    }

    // Fused chunk-max for S columns (whole CTA is in S when n0 < HIDDEN):
    // warp tile covers two 32-row chunks (mt 0,1 / mt 2,3).
    if (n0 < HIDDEN) {
        const int b_idx  = m0 >> 12;                       // batch
        const int chbase = ((m0 & 4095) >> 5) + (wm >> 5); // 32-row chunk idx
#pragma unroll
        for (int half = 0; half < 2; half++) {
#pragma unroll
            for (int nt = 0; nt < 8; nt++) {
                float v0 = NEG_INF, v1 = NEG_INF;
#pragma unroll
                for (int mt = 2 * half; mt < 2 * half + 2; mt++) {
                    v0 = fmaxf(v0, fmaxf(acc[mt][nt][0], acc[mt][nt][2]));
                    v1 = fmaxf(v1, fmaxf(acc[mt][nt][1], acc[mt][nt][3]));
                }
#pragma unroll
                for (int msk = 4; msk <= 16; msk <<= 1) {
                    v0 = fmaxf(v0, __shfl_xor_sync(0xffffffffu, v0, msk));
                    v1 = fmaxf(v1, __shfl_xor_sync(0xffffffffu, v1, msk));
                }
                if (lid < 4) {
                    int col = n0 + wn + nt * 8 + lid * 2;
                    int ch  = chbase + half;
                    g_cmax[((size_t)(b_idx * HIDDEN + col)) * NCH + ch]     = v0;
                    g_cmax[((size_t)(b_idx * HIDDEN + col + 1)) * NCH + ch] = v1;
                }
            }
        }
    }

    // Epilogue: fp16 stores to g_Yh
    const int r0l = lid >> 2;          // 0..7
    const int c0l = (lid & 3) * 2;     // 0,2,4,6
#pragma unroll
    for (int mt = 0; mt < 4; mt++) {
#pragma unroll
        for (int nt = 0; nt < 8; nt++) {
            size_t row = (size_t)(m0 + wm + mt * 16 + r0l);
            size_t col = (size_t)(n0 + wn + nt * 8 + c0l);
            __half2 h0 = __floats2half2_rn(acc[mt][nt][0], acc[mt][nt][1]);
            __half2 h1 = __floats2half2_rn(acc[mt][nt][2], acc[mt][nt][3]);
            *reinterpret_cast<__half2*>(g_Yh + row * NTOT + col) = h0;
            *reinterpret_cast<__half2*>(g_Yh + (row + 8) * NTOT + col) = h1;
        }
    }
}

// ---------------------------------------------------------------------------
// Prefix kernel: in-place convert g_cmax rows into EXCLUSIVE prefix maxes.
// ---------------------------------------------------------------------------
__global__ __launch_bounds__(128) void prefix_kernel() {
    __shared__ float s[NCH];
    const int tid = threadIdx.x;
    float* row = g_cmax + (size_t)blockIdx.x * NCH;
    float v = row[tid];
    s[tid] = v;
    __syncthreads();
#pragma unroll
    for (int off = 1; off < NCH; off <<= 1) {
        float t = (tid >= off) ? s[tid - off] : NEG_INF;
        __syncthreads();
        s[tid] = fmaxf(s[tid], t);
        __syncthreads();
    }
    float excl = (tid == 0) ? NEG_INF : s[tid - 1];
    row[tid] = excl;
}

// ---------------------------------------------------------------------------
// Finalize: run = prefix[ch]; in-chunk (32-row) cummax + epilogue
// out = (cm + out2) * cm + out1   (512 threads, 2 channels each)
// ---------------------------------------------------------------------------
__global__ __launch_bounds__(512) void finalize_kernel(float* __restrict__ out) {
    const int c  = threadIdx.x * 2;
    const int b  = blockIdx.x;
    const int ch = blockIdx.y;
    float run0 = g_cmax[((size_t)(b * HIDDEN + c)) * NCH + ch];
    float run1 = g_cmax[((size_t)(b * HIDDEN + c + 1)) * NCH + ch];
    const size_t row0 = (size_t)b * SEQ + (size_t)ch * CHUNK;
#pragma unroll 4
    for (int s = 0; s < CHUNK; s++) {
        const size_t row = row0 + s;
        const size_t yb  = row * NTOT;
        float2 sv = __half22float2(*reinterpret_cast<const __half2*>(g_Yh + yb + c));
        run0 = fmaxf(run0, sv.x);
        run1 = fmaxf(run1, sv.y);
        float2 o1 = __half22float2(*reinterpret_cast<const __half2*>(g_Yh + yb + HIDDEN + c));
        float2 o2 = __half22float2(*reinterpret_cast<const __half2*>(g_Yh + yb + 2 * HIDDEN + c));
        float2 r;
        r.x = (run0 + o2.x) * run0 + o1.x;
        r.y = (run1 + o2.y) * run1 + o1.y;
        *reinterpret_cast<float2*>(out + row * HIDDEN + c) = r;
    }
}

// ---------------------------------------------------------------------------
// Launch
// ---------------------------------------------------------------------------
extern "C" void kernel_launch(void* const* d_in, const int* in_sizes, int n_in,
                              void* d_out, int out_size) {
    const float* X  = (const float*)d_in[0];
    const float* W0 = (const float*)d_in[1];
    const float* W1 = (const float*)d_in[2];
    const float* W2 = (const float*)d_in[3];
    float* out = (float*)d_out;

    cudaFuncSetAttribute(gemm_kernel,
                         cudaFuncAttributeMaxDynamicSharedMemorySize, SMEM_TOTAL);

    prep_w_kernel<<<(NTOT * HIDDEN / 4) / 256, 256>>>(W0, W1, W2);
    prep_x_kernel<<<(int)(((size_t)MTOT * HIDDEN / 4) / 256), 256>>>(X);
    gemm_kernel<<<dim3(NTOT / BN, MTOT / BM), 256, SMEM_TOTAL>>>();
    prefix_kernel<<<BATCH * HIDDEN, 128>>>();
    finalize_kernel<<<dim3(BATCH, NCH), 512>>>(out);
}

// round 9
// speedup vs baseline: 1.0032x; 1.0032x over previous
#include <cuda_runtime.h>
#include <cuda_fp16.h>
#include <cstdint>

// ---------------------------------------------------------------------------
// Problem constants
// ---------------------------------------------------------------------------
#define BATCH   4
#define SEQ     4096
#define HIDDEN  1024
#define MTOT    (BATCH * SEQ)          // 16384
#define NTOT    (3 * HIDDEN)           // 3072 (S | out1 | out2)

// GEMM tiling: CTA 128x384, 12 warps of 64x64 (2m x 6n), BK=64
#define BM 128
#define BN 384
#define BK 64                           // 64 fp16 = 128 B row (SW128 swizzle)
#define NKT (HIDDEN / BK)               // 16 k-tiles
#define NTHR 384

#define A_BYTES 16384                   // 128 x 64 fp16
#define B_BYTES 49152                   // 384 x 64 fp16
#define STAGE_BYTES (A_BYTES + B_BYTES) // 64 KB
#define NSTAGE 3
#define SMEM_TOTAL (NSTAGE * STAGE_BYTES)    // 192 KB (<= ~227 KB on sm_103)

// Scan tiling: 32-row chunks
#define NCH   128
#define CHUNK 32

// ---------------------------------------------------------------------------
// Scratch (static device memory only; no allocations allowed)
// ---------------------------------------------------------------------------
__device__ __align__(256) __half         g_Yh[(size_t)MTOT * NTOT];       // 96 MB
__device__ __align__(256) unsigned short g_Xh[(size_t)MTOT * HIDDEN];     // 32 MB
__device__ __align__(256) unsigned short g_Wh[(size_t)NTOT * HIDDEN];     // 6 MB
__device__ __align__(256) float          g_cmax[(size_t)BATCH * HIDDEN * NCH]; // 2 MB

// ---------------------------------------------------------------------------
// Small helpers
// ---------------------------------------------------------------------------
__device__ __forceinline__ uint32_t smem_to_u32(const void* smem_ptr) {
    uint32_t addr;
    asm("{ .reg .u64 tmp; cvta.to.shared.u64 tmp, %1; cvt.u32.u64 %0, tmp; }"
        : "=r"(addr) : "l"(smem_ptr));
    return addr;
}

__device__ __forceinline__ void cp_async16(uint32_t saddr, const void* gaddr) {
    asm volatile("cp.async.cg.shared.global [%0], [%1], 16;"
                 :: "r"(saddr), "l"(gaddr));
}
__device__ __forceinline__ void cp_commit() {
    asm volatile("cp.async.commit_group;");
}
template <int N>
__device__ __forceinline__ void cp_wait() {
    asm volatile("cp.async.wait_group %0;" :: "n"(N));
}

__device__ __forceinline__ void ldmatrix_x4(uint32_t& r0, uint32_t& r1,
                                            uint32_t& r2, uint32_t& r3,
                                            uint32_t addr) {
    asm volatile("ldmatrix.sync.aligned.m8n8.x4.shared.b16 {%0,%1,%2,%3}, [%4];"
                 : "=r"(r0), "=r"(r1), "=r"(r2), "=r"(r3) : "r"(addr));
}

__device__ __forceinline__ void mma_f16(float* d, const uint32_t* a,
                                        const uint32_t* b) {
    asm volatile(
        "mma.sync.aligned.m16n8k16.row.col.f32.f16.f16.f32 "
        "{%0,%1,%2,%3}, {%4,%5,%6,%7}, {%8,%9}, {%0,%1,%2,%3};"
        : "+f"(d[0]), "+f"(d[1]), "+f"(d[2]), "+f"(d[3])
        : "r"(a[0]), "r"(a[1]), "r"(a[2]), "r"(a[3]), "r"(b[0]), "r"(b[1]));
}

#define NEG_INF __int_as_float(0xff800000)

// ---------------------------------------------------------------------------
// Prep kernels: fp16 of X; fp16 of Wcat = [(W0+W1)/8 ; W1 ; W2]
// ---------------------------------------------------------------------------
__global__ __launch_bounds__(256) void prep_x_kernel(const float* __restrict__ X) {
    size_t i = (size_t)blockIdx.x * blockDim.x + threadIdx.x;   // vec4 index
    float4 v = reinterpret_cast<const float4*>(X)[i];
    ushort4 h;
    h.x = __half_as_ushort(__float2half_rn(v.x));
    h.y = __half_as_ushort(__float2half_rn(v.y));
    h.z = __half_as_ushort(__float2half_rn(v.z));
    h.w = __half_as_ushort(__float2half_rn(v.w));
    reinterpret_cast<ushort4*>(g_Xh)[i] = h;
}

__global__ __launch_bounds__(256) void prep_w_kernel(const float* __restrict__ W0,
                                                     const float* __restrict__ W1,
                                                     const float* __restrict__ W2) {
    size_t i = (size_t)blockIdx.x * blockDim.x + threadIdx.x;   // vec4 index
    size_t e = i * 4;
    int n = (int)(e >> 10);
    float4 w;
    if (n < HIDDEN) {
        float4 a = *reinterpret_cast<const float4*>(W0 + e);
        float4 b = *reinterpret_cast<const float4*>(W1 + e);
        w = make_float4((a.x + b.x) * 0.125f, (a.y + b.y) * 0.125f,
                        (a.z + b.z) * 0.125f, (a.w + b.w) * 0.125f);
    } else if (n < 2 * HIDDEN) {
        w = *reinterpret_cast<const float4*>(W1 + (e - (size_t)HIDDEN * HIDDEN));
    } else {
        w = *reinterpret_cast<const float4*>(W2 + (e - (size_t)2 * HIDDEN * HIDDEN));
    }
    ushort4 h;
    h.x = __half_as_ushort(__float2half_rn(w.x));
    h.y = __half_as_ushort(__float2half_rn(w.y));
    h.z = __half_as_ushort(__float2half_rn(w.z));
    h.w = __half_as_ushort(__float2half_rn(w.w));
    reinterpret_cast<ushort4*>(g_Wh)[i] = h;
}

// ---------------------------------------------------------------------------
// GEMM: Yh[16384,3072] = fp16( Xh@Wh^T ); fused per-chunk max of S columns.
// CTA 128x384, 12 warps of 64x64. 3-stage cp.async pipeline, 1 CTA/SM.
// ---------------------------------------------------------------------------
__device__ __forceinline__ void load_stage(uint32_t sbuf, int kt,
                                           int m0, int n0, int tid) {
    const int k0 = kt << 6;
    // A: 128 rows x 8 chunks = 1024 chunks over 384 threads
    for (int id = tid; id < 1024; id += NTHR) {
        int row = id >> 3;
        int c   = id & 7;
        uint32_t off = (uint32_t)(row << 7) | (uint32_t)((c ^ (row & 7)) << 4);
        cp_async16(sbuf + off,
                   g_Xh + ((size_t)(m0 + row) << 10) + k0 + c * 8);
    }
    // B: 384 rows x 8 chunks = 3072 chunks = 8 per thread exactly
#pragma unroll
    for (int i = 0; i < 8; i++) {
        int id  = tid + i * NTHR;
        int row = id >> 3;
        int c   = id & 7;
        uint32_t off = (uint32_t)(row << 7) | (uint32_t)((c ^ (row & 7)) << 4);
        cp_async16(sbuf + A_BYTES + off,
                   g_Wh + ((size_t)(n0 + row) << 10) + k0 + c * 8);
    }
    cp_commit();
}

__global__ __launch_bounds__(NTHR, 1) void gemm_kernel() {
    extern __shared__ char smem[];
    const uint32_t smem_base = smem_to_u32(smem);
    const int tid = threadIdx.x;
    const int wid = tid >> 5;
    const int lid = tid & 31;
    const int n0 = blockIdx.x * BN;
    const int m0 = blockIdx.y * BM;

    // Warp layout: 2 (m) x 6 (n); warp tile 64 x 64
    const int wm = (wid & 1) * 64;
    const int wn = (wid >> 1) * 64;

    // ldmatrix lane geometry
    const int lrow = (lid & 7) + ((lid >> 3) & 1) * 8;   // row within 16-row tile
    const int lchk = (lid >> 4);                          // 0/1: k 16B chunk

    float acc[4][8][4];
#pragma unroll
    for (int mt = 0; mt < 4; mt++)
#pragma unroll
        for (int nt = 0; nt < 8; nt++)
#pragma unroll
            for (int j = 0; j < 4; j++) acc[mt][nt][j] = 0.0f;

    load_stage(smem_base, 0, m0, n0, tid);
    load_stage(smem_base + STAGE_BYTES, 1, m0, n0, tid);

#pragma unroll 1
    for (int kt = 0; kt < NKT; kt++) {
        if (kt == NKT - 1) cp_wait<0>();
        else               cp_wait<1>();
        __syncthreads();
        // Prefetch kt+2: its buffer was last read in iteration kt-1, which
        // every warp finished before the barrier above.
        if (kt + 2 < NKT) {
            uint32_t sb = smem_base + ((kt + 2) % NSTAGE) * STAGE_BYTES;
            load_stage(sb, kt + 2, m0, n0, tid);
        }

        const uint32_t sA = smem_base + (kt % NSTAGE) * STAGE_BYTES;
        const uint32_t sB = sA + A_BYTES;

#pragma unroll
        for (int s = 0; s < 4; s++) {        // 4 sub-steps of k16
            const int chunk = 2 * s + lchk;
            // A fragments: 4 m-tiles of 16 rows
            uint32_t a[4][4];
#pragma unroll
            for (int mt = 0; mt < 4; mt++) {
                int row = wm + mt * 16 + lrow;
                uint32_t addr = sA + (uint32_t)(row << 7)
                              + (uint32_t)((chunk ^ (row & 7)) << 4);
                ldmatrix_x4(a[mt][0], a[mt][1], a[mt][2], a[mt][3], addr);
            }
            // B: 8 n-tiles of 8 rows, loaded pairwise (4 x ldmatrix.x4)
#pragma unroll
            for (int np = 0; np < 4; np++) {
                int row = wn + np * 16 + lrow;
                uint32_t addr = sB + (uint32_t)(row << 7)
                              + (uint32_t)((chunk ^ (row & 7)) << 4);
                uint32_t r0, r1, r2, r3;
                ldmatrix_x4(r0, r1, r2, r3, addr);
                uint32_t b0[2] = {r0, r2};   // n rows 0-7 of pair
                uint32_t b1[2] = {r1, r3};   // n rows 8-15 of pair
#pragma unroll
                for (int mt = 0; mt < 4; mt++) {
                    mma_f16(acc[mt][2 * np],     a[mt], b0);
                    mma_f16(acc[mt][2 * np + 1], a[mt], b1);
                }
            }
        }
    }

    // Fused chunk-max for S columns. Warp tiles are 64 wide and the S
    // boundary (col 1024) is 64-aligned, so a per-warp test suffices.
    if (n0 + wn < HIDDEN) {
        const int b_idx  = m0 >> 12;                       // batch
        const int chbase = ((m0 & 4095) >> 5) + (wm >> 5); // 32-row chunk idx
#pragma unroll
        for (int half = 0; half < 2; half++) {
#pragma unroll
            for (int nt = 0; nt < 8; nt++) {
                float v0 = NEG_INF, v1 = NEG_INF;
#pragma unroll
                for (int mt = 2 * half; mt < 2 * half + 2; mt++) {
                    v0 = fmaxf(v0, fmaxf(acc[mt][nt][0], acc[mt][nt][2]));
                    v1 = fmaxf(v1, fmaxf(acc[mt][nt][1], acc[mt][nt][3]));
                }
#pragma unroll
                for (int msk = 4; msk <= 16; msk <<= 1) {
                    v0 = fmaxf(v0, __shfl_xor_sync(0xffffffffu, v0, msk));
                    v1 = fmaxf(v1, __shfl_xor_sync(0xffffffffu, v1, msk));
                }
                if (lid < 4) {
                    int col = n0 + wn + nt * 8 + lid * 2;
                    int ch  = chbase + half;
                    g_cmax[((size_t)(b_idx * HIDDEN + col)) * NCH + ch]     = v0;
                    g_cmax[((size_t)(b_idx * HIDDEN + col + 1)) * NCH + ch] = v1;
                }
            }
        }
    }

    // Epilogue: fp16 stores to g_Yh
    const int r0l = lid >> 2;          // 0..7
    const int c0l = (lid & 3) * 2;     // 0,2,4,6
#pragma unroll
    for (int mt = 0; mt < 4; mt++) {
#pragma unroll
        for (int nt = 0; nt < 8; nt++) {
            size_t row = (size_t)(m0 + wm + mt * 16 + r0l);
            size_t col = (size_t)(n0 + wn + nt * 8 + c0l);
            __half2 h0 = __floats2half2_rn(acc[mt][nt][0], acc[mt][nt][1]);
            __half2 h1 = __floats2half2_rn(acc[mt][nt][2], acc[mt][nt][3]);
            *reinterpret_cast<__half2*>(g_Yh + row * NTOT + col) = h0;
            *reinterpret_cast<__half2*>(g_Yh + (row + 8) * NTOT + col) = h1;
        }
    }
}

// ---------------------------------------------------------------------------
// Prefix kernel: in-place convert g_cmax rows into EXCLUSIVE prefix maxes.
// ---------------------------------------------------------------------------
__global__ __launch_bounds__(128) void prefix_kernel() {
    __shared__ float s[NCH];
    const int tid = threadIdx.x;
    float* row = g_cmax + (size_t)blockIdx.x * NCH;
    float v = row[tid];
    s[tid] = v;
    __syncthreads();
#pragma unroll
    for (int off = 1; off < NCH; off <<= 1) {
        float t = (tid >= off) ? s[tid - off] : NEG_INF;
        __syncthreads();
        s[tid] = fmaxf(s[tid], t);
        __syncthreads();
    }
    float excl = (tid == 0) ? NEG_INF : s[tid - 1];
    row[tid] = excl;
}

// ---------------------------------------------------------------------------
// Finalize: run = prefix[ch]; in-chunk (32-row) cummax + epilogue
// out = (cm + out2) * cm + out1   (512 threads, 2 channels each)
// ---------------------------------------------------------------------------
__global__ __launch_bounds__(512) void finalize_kernel(float* __restrict__ out) {
    const int c  = threadIdx.x * 2;
    const int b  = blockIdx.x;
    const int ch = blockIdx.y;
    float run0 = g_cmax[((size_t)(b * HIDDEN + c)) * NCH + ch];
    float run1 = g_cmax[((size_t)(b * HIDDEN + c + 1)) * NCH + ch];
    const size_t row0 = (size_t)b * SEQ + (size_t)ch * CHUNK;
#pragma unroll 4
    for (int s = 0; s < CHUNK; s++) {
        const size_t row = row0 + s;
        const size_t yb  = row * NTOT;
        float2 sv = __half22float2(*reinterpret_cast<const __half2*>(g_Yh + yb + c));
        run0 = fmaxf(run0, sv.x);
        run1 = fmaxf(run1, sv.y);
        float2 o1 = __half22float2(*reinterpret_cast<const __half2*>(g_Yh + yb + HIDDEN + c));
        float2 o2 = __half22float2(*reinterpret_cast<const __half2*>(g_Yh + yb + 2 * HIDDEN + c));
        float2 r;
        r.x = (run0 + o2.x) * run0 + o1.x;
        r.y = (run1 + o2.y) * run1 + o1.y;
        *reinterpret_cast<float2*>(out + row * HIDDEN + c) = r;
    }
}

// ---------------------------------------------------------------------------
// Launch
// ---------------------------------------------------------------------------
extern "C" void kernel_launch(void* const* d_in, const int* in_sizes, int n_in,
                              void* d_out, int out_size) {
    const float* X  = (const float*)d_in[0];
    const float* W0 = (const float*)d_in[1];
    const float* W1 = (const float*)d_in[2];
    const float* W2 = (const float*)d_in[3];
    float* out = (float*)d_out;

    cudaFuncSetAttribute(gemm_kernel,
                         cudaFuncAttributeMaxDynamicSharedMemorySize, SMEM_TOTAL);

    prep_w_kernel<<<(NTOT * HIDDEN / 4) / 256, 256>>>(W0, W1, W2);
    prep_x_kernel<<<(int)(((size_t)MTOT * HIDDEN / 4) / 256), 256>>>(X);
    gemm_kernel<<<dim3(NTOT / BN, MTOT / BM), NTHR, SMEM_TOTAL>>>();
    prefix_kernel<<<BATCH * HIDDEN, 128>>>();
    finalize_kernel<<<dim3(BATCH, NCH), 512>>>(out);
}

// round 10
// speedup vs baseline: 1.0607x; 1.0574x over previous
#include <cuda_runtime.h>
#include <cuda_fp16.h>
#include <cstdint>

// ---------------------------------------------------------------------------
// Problem constants
// ---------------------------------------------------------------------------
#define BATCH   4
#define SEQ     4096
#define HIDDEN  1024
#define MTOT    (BATCH * SEQ)          // 16384
#define NTOT    (3 * HIDDEN)           // 3072 (S | out1 | out2)

// GEMM tiling: CTA 128x128, 8 warps of 64x32, BK=64 (R7 optimum config)
#define BM 128
#define BN 128
#define BK 64                           // 64 fp16 = 128 B row (SW128 swizzle)
#define NKT (HIDDEN / BK)               // 16 k-tiles

#define TILE_BYTES  16384               // 128 x 64 fp16
#define STAGE_BYTES (2 * TILE_BYTES)    // A + B = 32 KB
#define NSTAGE 3
#define SMEM_TOTAL  (NSTAGE * STAGE_BYTES)   // 96 KB, 2 CTAs/SM

// Scan tiling: 32-row chunks
#define NCH   128
#define CHUNK 32

// ---------------------------------------------------------------------------
// Scratch (static device memory only; no allocations allowed)
// ---------------------------------------------------------------------------
__device__ __align__(256) __half         g_Yh[(size_t)MTOT * NTOT];       // 96 MB
__device__ __align__(256) unsigned short g_Xh[(size_t)MTOT * HIDDEN];     // 32 MB
__device__ __align__(256) unsigned short g_Wh[(size_t)NTOT * HIDDEN];     // 6 MB
__device__ __align__(256) float          g_cmax[(size_t)BATCH * HIDDEN * NCH]; // 2 MB

// ---------------------------------------------------------------------------
// Small helpers
// ---------------------------------------------------------------------------
__device__ __forceinline__ uint32_t smem_to_u32(const void* smem_ptr) {
    uint32_t addr;
    asm("{ .reg .u64 tmp; cvta.to.shared.u64 tmp, %1; cvt.u32.u64 %0, tmp; }"
        : "=r"(addr) : "l"(smem_ptr));
    return addr;
}

__device__ __forceinline__ void cp_async16(uint32_t saddr, const void* gaddr) {
    asm volatile("cp.async.cg.shared.global [%0], [%1], 16;"
                 :: "r"(saddr), "l"(gaddr));
}
__device__ __forceinline__ void cp_commit() {
    asm volatile("cp.async.commit_group;");
}
template <int N>
__device__ __forceinline__ void cp_wait() {
    asm volatile("cp.async.wait_group %0;" :: "n"(N));
}

__device__ __forceinline__ void ldmatrix_x4(uint32_t& r0, uint32_t& r1,
                                            uint32_t& r2, uint32_t& r3,
                                            uint32_t addr) {
    asm volatile("ldmatrix.sync.aligned.m8n8.x4.shared.b16 {%0,%1,%2,%3}, [%4];"
                 : "=r"(r0), "=r"(r1), "=r"(r2), "=r"(r3) : "r"(addr));
}

__device__ __forceinline__ void mma_f16(float* d, const uint32_t* a,
                                        const uint32_t* b) {
    asm volatile(
        "mma.sync.aligned.m16n8k16.row.col.f32.f16.f16.f32 "
        "{%0,%1,%2,%3}, {%4,%5,%6,%7}, {%8,%9}, {%0,%1,%2,%3};"
        : "+f"(d[0]), "+f"(d[1]), "+f"(d[2]), "+f"(d[3])
        : "r"(a[0]), "r"(a[1]), "r"(a[2]), "r"(a[3]), "r"(b[0]), "r"(b[1]));
}

#define NEG_INF __int_as_float(0xff800000)

// ---------------------------------------------------------------------------
// Prep kernels: fp16 of X; fp16 of Wcat = [(W0+W1)/8 ; W1 ; W2]
// ---------------------------------------------------------------------------
__global__ __launch_bounds__(256) void prep_x_kernel(const float* __restrict__ X) {
    size_t i = (size_t)blockIdx.x * blockDim.x + threadIdx.x;   // vec4 index
    float4 v = reinterpret_cast<const float4*>(X)[i];
    ushort4 h;
    h.x = __half_as_ushort(__float2half_rn(v.x));
    h.y = __half_as_ushort(__float2half_rn(v.y));
    h.z = __half_as_ushort(__float2half_rn(v.z));
    h.w = __half_as_ushort(__float2half_rn(v.w));
    reinterpret_cast<ushort4*>(g_Xh)[i] = h;
}

__global__ __launch_bounds__(256) void prep_w_kernel(const float* __restrict__ W0,
                                                     const float* __restrict__ W1,
                                                     const float* __restrict__ W2) {
    size_t i = (size_t)blockIdx.x * blockDim.x + threadIdx.x;   // vec4 index
    size_t e = i * 4;
    int n = (int)(e >> 10);
    float4 w;
    if (n < HIDDEN) {
        float4 a = *reinterpret_cast<const float4*>(W0 + e);
        float4 b = *reinterpret_cast<const float4*>(W1 + e);
        w = make_float4((a.x + b.x) * 0.125f, (a.y + b.y) * 0.125f,
                        (a.z + b.z) * 0.125f, (a.w + b.w) * 0.125f);
    } else if (n < 2 * HIDDEN) {
        w = *reinterpret_cast<const float4*>(W1 + (e - (size_t)HIDDEN * HIDDEN));
    } else {
        w = *reinterpret_cast<const float4*>(W2 + (e - (size_t)2 * HIDDEN * HIDDEN));
    }
    ushort4 h;
    h.x = __half_as_ushort(__float2half_rn(w.x));
    h.y = __half_as_ushort(__float2half_rn(w.y));
    h.z = __half_as_ushort(__float2half_rn(w.z));
    h.w = __half_as_ushort(__float2half_rn(w.w));
    reinterpret_cast<ushort4*>(g_Wh)[i] = h;
}

// ---------------------------------------------------------------------------
// GEMM: Yh[16384,3072] = fp16( Xh@Wh^T ); fused per-chunk max of S columns.
// CTA 128x128, 8 warps of 64x32, 3-stage cp.async pipeline, 2 CTAs/SM.
// ---------------------------------------------------------------------------
__device__ __forceinline__ void load_stage(uint32_t sbuf, int kt,
                                           int m0, int n0, int tid) {
    const int k0 = kt << 6;
#pragma unroll
    for (int i = 0; i < 4; i++) {
        int id  = tid + i * 256;
        int row = id >> 3;
        int c   = id & 7;
        uint32_t off = (uint32_t)(row << 7) | (uint32_t)((c ^ (row & 7)) << 4);
        cp_async16(sbuf + off,
                   g_Xh + ((size_t)(m0 + row) << 10) + k0 + c * 8);
        cp_async16(sbuf + TILE_BYTES + off,
                   g_Wh + ((size_t)(n0 + row) << 10) + k0 + c * 8);
    }
    cp_commit();
}

// Load one substep's fragments (A: 4 m-tiles, B: 4 n-tiles pairwise).
__device__ __forceinline__ void load_frags(uint32_t sA, uint32_t sB, int chunk,
                                           int wm, int wn, int lrow,
                                           uint32_t a[4][4], uint32_t b[4][2]) {
#pragma unroll
    for (int np = 0; np < 2; np++) {
        int row = wn + np * 16 + lrow;
        uint32_t addr = sB + (uint32_t)(row << 7)
                      + (uint32_t)((chunk ^ (row & 7)) << 4);
        uint32_t r0, r1, r2, r3;
        ldmatrix_x4(r0, r1, r2, r3, addr);
        b[2 * np][0] = r0;     b[2 * np][1] = r2;
        b[2 * np + 1][0] = r1; b[2 * np + 1][1] = r3;
    }
#pragma unroll
    for (int mt = 0; mt < 4; mt++) {
        int row = wm + mt * 16 + lrow;
        uint32_t addr = sA + (uint32_t)(row << 7)
                      + (uint32_t)((chunk ^ (row & 7)) << 4);
        ldmatrix_x4(a[mt][0], a[mt][1], a[mt][2], a[mt][3], addr);
    }
}

__global__ __launch_bounds__(256, 2) void gemm_kernel() {
    extern __shared__ char smem[];
    const uint32_t smem_base = smem_to_u32(smem);
    const int tid = threadIdx.x;
    const int wid = tid >> 5;
    const int lid = tid & 31;
    const int n0 = blockIdx.x * BN;
    const int m0 = blockIdx.y * BM;

    // Warp layout: 2 (m) x 4 (n); warp tile 64 x 32
    const int wm = (wid & 1) * 64;
    const int wn = (wid >> 1) * 32;

    // ldmatrix lane geometry
    const int lrow = (lid & 7) + ((lid >> 3) & 1) * 8;   // row within 16-row tile
    const int lchk = (lid >> 4);                          // 0/1: k 16B chunk

    float acc[4][4][4];
#pragma unroll
    for (int mt = 0; mt < 4; mt++)
#pragma unroll
        for (int nt = 0; nt < 4; nt++)
#pragma unroll
            for (int j = 0; j < 4; j++) acc[mt][nt][j] = 0.0f;

    load_stage(smem_base, 0, m0, n0, tid);
    load_stage(smem_base + STAGE_BYTES, 1, m0, n0, tid);

#pragma unroll 1
    for (int kt = 0; kt < NKT; kt++) {
        if (kt == NKT - 1) cp_wait<0>();
        else               cp_wait<1>();
        __syncthreads();

        const uint32_t sA = smem_base + (kt % NSTAGE) * STAGE_BYTES;
        const uint32_t sB = sA + TILE_BYTES;

        uint32_t a[4][4], b[4][2];
        // Substep 0 fragment loads FIRST, so the prefetch cp.asyncs below
        // issue inside the LDS latency shadow instead of delaying them.
        load_frags(sA, sB, lchk, wm, wn, lrow, a, b);

        // Prefetch kt+2: its buffer was last read in iteration kt-1, which
        // every warp finished before the barrier above.
        if (kt + 2 < NKT) {
            uint32_t sb = smem_base + ((kt + 2) % NSTAGE) * STAGE_BYTES;
            load_stage(sb, kt + 2, m0, n0, tid);
        }

#pragma unroll
        for (int mt = 0; mt < 4; mt++)
#pragma unroll
            for (int nt = 0; nt < 4; nt++)
                mma_f16(acc[mt][nt], a[mt], b[nt]);

#pragma unroll
        for (int s = 1; s < 4; s++) {        // remaining 3 sub-steps of k16
            const int chunk = 2 * s + lchk;
            load_frags(sA, sB, chunk, wm, wn, lrow, a, b);
#pragma unroll
            for (int mt = 0; mt < 4; mt++)
#pragma unroll
                for (int nt = 0; nt < 4; nt++)
                    mma_f16(acc[mt][nt], a[mt], b[nt]);
        }
    }

    // Fused chunk-max for S columns (n0 < HIDDEN): warp tile covers two
    // 32-row chunks (mt 0,1 -> rows 0..31; mt 2,3 -> rows 32..63).
    if (n0 < HIDDEN) {
        const int b_idx  = m0 >> 12;                       // batch
        const int chbase = ((m0 & 4095) >> 5) + (wm >> 5); // 32-row chunk idx
#pragma unroll
        for (int half = 0; half < 2; half++) {
#pragma unroll
            for (int nt = 0; nt < 4; nt++) {
                float v0 = NEG_INF, v1 = NEG_INF;
#pragma unroll
                for (int mt = 2 * half; mt < 2 * half + 2; mt++) {
                    v0 = fmaxf(v0, fmaxf(acc[mt][nt][0], acc[mt][nt][2]));
                    v1 = fmaxf(v1, fmaxf(acc[mt][nt][1], acc[mt][nt][3]));
                }
#pragma unroll
                for (int msk = 4; msk <= 16; msk <<= 1) {
                    v0 = fmaxf(v0, __shfl_xor_sync(0xffffffffu, v0, msk));
                    v1 = fmaxf(v1, __shfl_xor_sync(0xffffffffu, v1, msk));
                }
                if (lid < 4) {
                    int col = n0 + wn + nt * 8 + lid * 2;
                    int ch  = chbase + half;
                    g_cmax[((size_t)(b_idx * HIDDEN + col)) * NCH + ch]     = v0;
                    g_cmax[((size_t)(b_idx * HIDDEN + col + 1)) * NCH + ch] = v1;
                }
            }
        }
    }

    // Epilogue: fp16 stores to g_Yh
    const int r0l = lid >> 2;          // 0..7
    const int c0l = (lid & 3) * 2;     // 0,2,4,6
#pragma unroll
    for (int mt = 0; mt < 4; mt++) {
#pragma unroll
        for (int nt = 0; nt < 4; nt++) {
            size_t row = (size_t)(m0 + wm + mt * 16 + r0l);
            size_t col = (size_t)(n0 + wn + nt * 8 + c0l);
            __half2 h0 = __floats2half2_rn(acc[mt][nt][0], acc[mt][nt][1]);
            __half2 h1 = __floats2half2_rn(acc[mt][nt][2], acc[mt][nt][3]);
            *reinterpret_cast<__half2*>(g_Yh + row * NTOT + col) = h0;
            *reinterpret_cast<__half2*>(g_Yh + (row + 8) * NTOT + col) = h1;
        }
    }
}

// ---------------------------------------------------------------------------
// Prefix kernel: convert g_cmax rows (length 128) into EXCLUSIVE prefix
// maxes in-place. One WARP per row; float4 + shfl_up scan. Exact (max assoc).
// ---------------------------------------------------------------------------
__global__ __launch_bounds__(256) void prefix_kernel() {
    const int lane = threadIdx.x & 31;
    const int wrp  = threadIdx.x >> 5;
    float* row = g_cmax + ((size_t)blockIdx.x * 8 + wrp) * NCH;
    float4 v = reinterpret_cast<float4*>(row)[lane];
    float t = fmaxf(fmaxf(v.x, v.y), fmaxf(v.z, v.w));
    // inclusive warp scan (max)
#pragma unroll
    for (int off = 1; off < 32; off <<= 1) {
        float u = __shfl_up_sync(0xffffffffu, t, off);
        if (lane >= off) t = fmaxf(t, u);
    }
    float excl = __shfl_up_sync(0xffffffffu, t, 1);
    if (lane == 0) excl = NEG_INF;
    float4 e;
    e.x = excl;
    e.y = fmaxf(excl, v.x);
    e.z = fmaxf(e.y, v.y);
    e.w = fmaxf(e.z, v.z);
    reinterpret_cast<float4*>(row)[lane] = e;
}

// ---------------------------------------------------------------------------
// Finalize: run = prefix[ch]; in-chunk (32-row) cummax + epilogue
// out = (cm + out2) * cm + out1   (512 threads, 2 channels each)
// ---------------------------------------------------------------------------
__global__ __launch_bounds__(512) void finalize_kernel(float* __restrict__ out) {
    const int c  = threadIdx.x * 2;
    const int b  = blockIdx.x;
    const int ch = blockIdx.y;
    float run0 = g_cmax[((size_t)(b * HIDDEN + c)) * NCH + ch];
    float run1 = g_cmax[((size_t)(b * HIDDEN + c + 1)) * NCH + ch];
    const size_t row0 = (size_t)b * SEQ + (size_t)ch * CHUNK;
#pragma unroll 4
    for (int s = 0; s < CHUNK; s++) {
        const size_t row = row0 + s;
        const size_t yb  = row * NTOT;
        float2 sv = __half22float2(*reinterpret_cast<const __half2*>(g_Yh + yb + c));
        run0 = fmaxf(run0, sv.x);
        run1 = fmaxf(run1, sv.y);
        float2 o1 = __half22float2(*reinterpret_cast<const __half2*>(g_Yh + yb + HIDDEN + c));
        float2 o2 = __half22float2(*reinterpret_cast<const __half2*>(g_Yh + yb + 2 * HIDDEN + c));
        float2 r;
        r.x = (run0 + o2.x) * run0 + o1.x;
        r.y = (run1 + o2.y) * run1 + o1.y;
        *reinterpret_cast<float2*>(out + row * HIDDEN + c) = r;
    }
}

// ---------------------------------------------------------------------------
// Launch
// ---------------------------------------------------------------------------
extern "C" void kernel_launch(void* const* d_in, const int* in_sizes, int n_in,
                              void* d_out, int out_size) {
    const float* X  = (const float*)d_in[0];
    const float* W0 = (const float*)d_in[1];
    const float* W1 = (const float*)d_in[2];
    const float* W2 = (const float*)d_in[3];
    float* out = (float*)d_out;

    cudaFuncSetAttribute(gemm_kernel,
                         cudaFuncAttributeMaxDynamicSharedMemorySize, SMEM_TOTAL);

    prep_w_kernel<<<(NTOT * HIDDEN / 4) / 256, 256>>>(W0, W1, W2);
    prep_x_kernel<<<(int)(((size_t)MTOT * HIDDEN / 4) / 256), 256>>>(X);
    gemm_kernel<<<dim3(NTOT / BN, MTOT / BM), 256, SMEM_TOTAL>>>();
    prefix_kernel<<<(BATCH * HIDDEN) / 8, 256>>>();
    finalize_kernel<<<dim3(BATCH, NCH), 512>>>(out);
}

// round 11
// speedup vs baseline: 1.0948x; 1.0322x over previous
#include <cuda_runtime.h>
#include <cuda_fp16.h>
#include <cstdint>

// ---------------------------------------------------------------------------
// Problem constants
// ---------------------------------------------------------------------------
#define BATCH   4
#define SEQ     4096
#define HIDDEN  1024
#define MTOT    (BATCH * SEQ)          // 16384
#define NTOT    (3 * HIDDEN)           // 3072 (S | out1 | out2)

// GEMM tiling: CTA 128x128, 8 warps of 64x32, BK=64 (R7 optimum config)
#define BM 128
#define BN 128
#define BK 64                           // 64 fp16 = 128 B row (SW128 swizzle)
#define NKT (HIDDEN / BK)               // 16 k-tiles

#define TILE_BYTES  16384               // 128 x 64 fp16
#define STAGE_BYTES (2 * TILE_BYTES)    // A + B = 32 KB
#define NSTAGE 3
#define SMEM_TOTAL  (NSTAGE * STAGE_BYTES)   // 96 KB, 2 CTAs/SM

// Scan tiling: 32-row chunks
#define NCH   128
#define CHUNK 32

// Prep sizes (vec4 units)
#define W_VEC4 ((NTOT * HIDDEN) / 4)                  // 786432
#define X_VEC4 ((int)(((size_t)MTOT * HIDDEN) / 4))   // 4194304

// ---------------------------------------------------------------------------
// Scratch (static device memory only; no allocations allowed)
// ---------------------------------------------------------------------------
__device__ __align__(256) __half         g_Yh[(size_t)MTOT * NTOT];       // 96 MB
__device__ __align__(256) unsigned short g_Xh[(size_t)MTOT * HIDDEN];     // 32 MB
__device__ __align__(256) unsigned short g_Wh[(size_t)NTOT * HIDDEN];     // 6 MB
__device__ __align__(256) float          g_cmax[(size_t)BATCH * HIDDEN * NCH]; // 2 MB

// ---------------------------------------------------------------------------
// Small helpers
// ---------------------------------------------------------------------------
__device__ __forceinline__ uint32_t smem_to_u32(const void* smem_ptr) {
    uint32_t addr;
    asm("{ .reg .u64 tmp; cvta.to.shared.u64 tmp, %1; cvt.u32.u64 %0, tmp; }"
        : "=r"(addr) : "l"(smem_ptr));
    return addr;
}

__device__ __forceinline__ void cp_async16(uint32_t saddr, const void* gaddr) {
    asm volatile("cp.async.cg.shared.global [%0], [%1], 16;"
                 :: "r"(saddr), "l"(gaddr));
}
__device__ __forceinline__ void cp_commit() {
    asm volatile("cp.async.commit_group;");
}
template <int N>
__device__ __forceinline__ void cp_wait() {
    asm volatile("cp.async.wait_group %0;" :: "n"(N));
}

__device__ __forceinline__ void ldmatrix_x4(uint32_t& r0, uint32_t& r1,
                                            uint32_t& r2, uint32_t& r3,
                                            uint32_t addr) {
    asm volatile("ldmatrix.sync.aligned.m8n8.x4.shared.b16 {%0,%1,%2,%3}, [%4];"
                 : "=r"(r0), "=r"(r1), "=r"(r2), "=r"(r3) : "r"(addr));
}

__device__ __forceinline__ void mma_f16(float* d, const uint32_t* a,
                                        const uint32_t* b) {
    asm volatile(
        "mma.sync.aligned.m16n8k16.row.col.f32.f16.f16.f32 "
        "{%0,%1,%2,%3}, {%4,%5,%6,%7}, {%8,%9}, {%0,%1,%2,%3};"
        : "+f"(d[0]), "+f"(d[1]), "+f"(d[2]), "+f"(d[3])
        : "r"(a[0]), "r"(a[1]), "r"(a[2]), "r"(a[3]), "r"(b[0]), "r"(b[1]));
}

#define NEG_INF __int_as_float(0xff800000)

// ---------------------------------------------------------------------------
// Merged prep: blocks [0, W_VEC4/256) convert Wcat; the rest convert X.
// Wcat = [(W0+W1)/8 ; W1 ; W2], all fp16.
// ---------------------------------------------------------------------------
__global__ __launch_bounds__(256) void prep_kernel(const float* __restrict__ X,
                                                   const float* __restrict__ W0,
                                                   const float* __restrict__ W1,
                                                   const float* __restrict__ W2) {
    size_t gi = (size_t)blockIdx.x * blockDim.x + threadIdx.x;
    if (gi < W_VEC4) {
        size_t e = gi * 4;
        int n = (int)(e >> 10);
        float4 w;
        if (n < HIDDEN) {
            float4 a = *reinterpret_cast<const float4*>(W0 + e);
            float4 b = *reinterpret_cast<const float4*>(W1 + e);
            w = make_float4((a.x + b.x) * 0.125f, (a.y + b.y) * 0.125f,
                            (a.z + b.z) * 0.125f, (a.w + b.w) * 0.125f);
        } else if (n < 2 * HIDDEN) {
            w = *reinterpret_cast<const float4*>(W1 + (e - (size_t)HIDDEN * HIDDEN));
        } else {
            w = *reinterpret_cast<const float4*>(W2 + (e - (size_t)2 * HIDDEN * HIDDEN));
        }
        ushort4 h;
        h.x = __half_as_ushort(__float2half_rn(w.x));
        h.y = __half_as_ushort(__float2half_rn(w.y));
        h.z = __half_as_ushort(__float2half_rn(w.z));
        h.w = __half_as_ushort(__float2half_rn(w.w));
        reinterpret_cast<ushort4*>(g_Wh)[gi] = h;
    } else {
        size_t i = gi - W_VEC4;
        float4 v = reinterpret_cast<const float4*>(X)[i];
        ushort4 h;
        h.x = __half_as_ushort(__float2half_rn(v.x));
        h.y = __half_as_ushort(__float2half_rn(v.y));
        h.z = __half_as_ushort(__float2half_rn(v.z));
        h.w = __half_as_ushort(__float2half_rn(v.w));
        reinterpret_cast<ushort4*>(g_Xh)[i] = h;
    }
}

// ---------------------------------------------------------------------------
// GEMM: Yh[16384,3072] = fp16( Xh@Wh^T ); fused per-chunk max of S columns.
// CTA 128x128, 8 warps of 64x32, 3-stage cp.async pipeline, 2 CTAs/SM.
// (R7 ordering: wait -> sync -> prefetch -> compute.)
// ---------------------------------------------------------------------------
__device__ __forceinline__ void load_stage(uint32_t sbuf, int kt,
                                           int m0, int n0, int tid) {
    const int k0 = kt << 6;
#pragma unroll
    for (int i = 0; i < 4; i++) {
        int id  = tid + i * 256;
        int row = id >> 3;
        int c   = id & 7;
        uint32_t off = (uint32_t)(row << 7) | (uint32_t)((c ^ (row & 7)) << 4);
        cp_async16(sbuf + off,
                   g_Xh + ((size_t)(m0 + row) << 10) + k0 + c * 8);
        cp_async16(sbuf + TILE_BYTES + off,
                   g_Wh + ((size_t)(n0 + row) << 10) + k0 + c * 8);
    }
    cp_commit();
}

__global__ __launch_bounds__(256, 2) void gemm_kernel() {
    extern __shared__ char smem[];
    const uint32_t smem_base = smem_to_u32(smem);
    const int tid = threadIdx.x;
    const int wid = tid >> 5;
    const int lid = tid & 31;
    const int n0 = blockIdx.x * BN;
    const int m0 = blockIdx.y * BM;

    // Warp layout: 2 (m) x 4 (n); warp tile 64 x 32
    const int wm = (wid & 1) * 64;
    const int wn = (wid >> 1) * 32;

    // ldmatrix lane geometry
    const int lrow = (lid & 7) + ((lid >> 3) & 1) * 8;   // row within 16-row tile
    const int lchk = (lid >> 4);                          // 0/1: k 16B chunk

    float acc[4][4][4];
#pragma unroll
    for (int mt = 0; mt < 4; mt++)
#pragma unroll
        for (int nt = 0; nt < 4; nt++)
#pragma unroll
            for (int j = 0; j < 4; j++) acc[mt][nt][j] = 0.0f;

    load_stage(smem_base, 0, m0, n0, tid);
    load_stage(smem_base + STAGE_BYTES, 1, m0, n0, tid);

#pragma unroll 1
    for (int kt = 0; kt < NKT; kt++) {
        if (kt == NKT - 1) cp_wait<0>();
        else               cp_wait<1>();
        __syncthreads();
        // Prefetch kt+2: its buffer was last read in iteration kt-1, which
        // every warp finished before the barrier above.
        if (kt + 2 < NKT) {
            uint32_t sb = smem_base + ((kt + 2) % NSTAGE) * STAGE_BYTES;
            load_stage(sb, kt + 2, m0, n0, tid);
        }

        const uint32_t sA = smem_base + (kt % NSTAGE) * STAGE_BYTES;
        const uint32_t sB = sA + TILE_BYTES;

#pragma unroll
        for (int s = 0; s < 4; s++) {        // 4 sub-steps of k16
            const int chunk = 2 * s + lchk;
            // B fragments: 4 n-tiles of 8 rows
            uint32_t b[4][2];
#pragma unroll
            for (int np = 0; np < 2; np++) {
                int row = wn + np * 16 + lrow;
                uint32_t addr = sB + (uint32_t)(row << 7)
                              + (uint32_t)((chunk ^ (row & 7)) << 4);
                uint32_t r0, r1, r2, r3;
                ldmatrix_x4(r0, r1, r2, r3, addr);
                b[2 * np][0] = r0;     b[2 * np][1] = r2;
                b[2 * np + 1][0] = r1; b[2 * np + 1][1] = r3;
            }
            // A fragments: 4 m-tiles of 16 rows
            uint32_t a[4][4];
#pragma unroll
            for (int mt = 0; mt < 4; mt++) {
                int row = wm + mt * 16 + lrow;
                uint32_t addr = sA + (uint32_t)(row << 7)
                              + (uint32_t)((chunk ^ (row & 7)) << 4);
                ldmatrix_x4(a[mt][0], a[mt][1], a[mt][2], a[mt][3], addr);
            }
#pragma unroll
            for (int mt = 0; mt < 4; mt++)
#pragma unroll
                for (int nt = 0; nt < 4; nt++)
                    mma_f16(acc[mt][nt], a[mt], b[nt]);
        }
    }

    // Fused chunk-max for S columns (n0 < HIDDEN): warp tile covers two
    // 32-row chunks (mt 0,1 -> rows 0..31; mt 2,3 -> rows 32..63).
    if (n0 < HIDDEN) {
        const int b_idx  = m0 >> 12;                       // batch
        const int chbase = ((m0 & 4095) >> 5) + (wm >> 5); // 32-row chunk idx
#pragma unroll
        for (int half = 0; half < 2; half++) {
#pragma unroll
            for (int nt = 0; nt < 4; nt++) {
                float v0 = NEG_INF, v1 = NEG_INF;
#pragma unroll
                for (int mt = 2 * half; mt < 2 * half + 2; mt++) {
                    v0 = fmaxf(v0, fmaxf(acc[mt][nt][0], acc[mt][nt][2]));
                    v1 = fmaxf(v1, fmaxf(acc[mt][nt][1], acc[mt][nt][3]));
                }
#pragma unroll
                for (int msk = 4; msk <= 16; msk <<= 1) {
                    v0 = fmaxf(v0, __shfl_xor_sync(0xffffffffu, v0, msk));
                    v1 = fmaxf(v1, __shfl_xor_sync(0xffffffffu, v1, msk));
                }
                if (lid < 4) {
                    int col = n0 + wn + nt * 8 + lid * 2;
                    int ch  = chbase + half;
                    g_cmax[((size_t)(b_idx * HIDDEN + col)) * NCH + ch]     = v0;
                    g_cmax[((size_t)(b_idx * HIDDEN + col + 1)) * NCH + ch] = v1;
                }
            }
        }
    }

    // Epilogue: fp16 stores to g_Yh
    const int r0l = lid >> 2;          // 0..7
    const int c0l = (lid & 3) * 2;     // 0,2,4,6
#pragma unroll
    for (int mt = 0; mt < 4; mt++) {
#pragma unroll
        for (int nt = 0; nt < 4; nt++) {
            size_t row = (size_t)(m0 + wm + mt * 16 + r0l);
            size_t col = (size_t)(n0 + wn + nt * 8 + c0l);
            __half2 h0 = __floats2half2_rn(acc[mt][nt][0], acc[mt][nt][1]);
            __half2 h1 = __floats2half2_rn(acc[mt][nt][2], acc[mt][nt][3]);
            *reinterpret_cast<__half2*>(g_Yh + row * NTOT + col) = h0;
            *reinterpret_cast<__half2*>(g_Yh + (row + 8) * NTOT + col) = h1;
        }
    }
}

// ---------------------------------------------------------------------------
// Prefix kernel: convert g_cmax rows (length 128) into EXCLUSIVE prefix
// maxes in-place. One WARP per row; float4 + shfl_up scan. Exact (max assoc).
// ---------------------------------------------------------------------------
__global__ __launch_bounds__(256) void prefix_kernel() {
    const int lane = threadIdx.x & 31;
    const int wrp  = threadIdx.x >> 5;
    float* row = g_cmax + ((size_t)blockIdx.x * 8 + wrp) * NCH;
    float4 v = reinterpret_cast<float4*>(row)[lane];
    float t = fmaxf(fmaxf(v.x, v.y), fmaxf(v.z, v.w));
#pragma unroll
    for (int off = 1; off < 32; off <<= 1) {
        float u = __shfl_up_sync(0xffffffffu, t, off);
        if (lane >= off) t = fmaxf(t, u);
    }
    float excl = __shfl_up_sync(0xffffffffu, t, 1);
    if (lane == 0) excl = NEG_INF;
    float4 e;
    e.x = excl;
    e.y = fmaxf(excl, v.x);
    e.z = fmaxf(e.y, v.y);
    e.w = fmaxf(e.z, v.z);
    reinterpret_cast<float4*>(row)[lane] = e;
}

// ---------------------------------------------------------------------------
// Finalize: run = prefix[ch]; in-chunk (32-row) cummax + epilogue
// out = (cm + out2) * cm + out1   (256 threads, 4 channels each, uint2 loads)
// ---------------------------------------------------------------------------
__global__ __launch_bounds__(256) void finalize_kernel(float* __restrict__ out) {
    const int c  = threadIdx.x * 4;
    const int b  = blockIdx.x;
    const int ch = blockIdx.y;
    float run[4];
#pragma unroll
    for (int j = 0; j < 4; j++)
        run[j] = g_cmax[((size_t)(b * HIDDEN + c + j)) * NCH + ch];
    const size_t row0 = (size_t)b * SEQ + (size_t)ch * CHUNK;
#pragma unroll 2
    for (int s = 0; s < CHUNK; s++) {
        const size_t row = row0 + s;
        const size_t yb  = row * NTOT;
        uint2 svu = *reinterpret_cast<const uint2*>(g_Yh + yb + c);
        uint2 o1u = *reinterpret_cast<const uint2*>(g_Yh + yb + HIDDEN + c);
        uint2 o2u = *reinterpret_cast<const uint2*>(g_Yh + yb + 2 * HIDDEN + c);
        float2 sv01 = __half22float2(*reinterpret_cast<__half2*>(&svu.x));
        float2 sv23 = __half22float2(*reinterpret_cast<__half2*>(&svu.y));
        float2 o101 = __half22float2(*reinterpret_cast<__half2*>(&o1u.x));
        float2 o123 = __half22float2(*reinterpret_cast<__half2*>(&o1u.y));
        float2 o201 = __half22float2(*reinterpret_cast<__half2*>(&o2u.x));
        float2 o223 = __half22float2(*reinterpret_cast<__half2*>(&o2u.y));
        run[0] = fmaxf(run[0], sv01.x);
        run[1] = fmaxf(run[1], sv01.y);
        run[2] = fmaxf(run[2], sv23.x);
        run[3] = fmaxf(run[3], sv23.y);
        float4 r;
        r.x = (run[0] + o201.x) * run[0] + o101.x;
        r.y = (run[1] + o201.y) * run[1] + o101.y;
        r.z = (run[2] + o223.x) * run[2] + o123.x;
        r.w = (run[3] + o223.y) * run[3] + o123.y;
        *reinterpret_cast<float4*>(out + row * HIDDEN + c) = r;
    }
}

// ---------------------------------------------------------------------------
// Launch
// ---------------------------------------------------------------------------
extern "C" void kernel_launch(void* const* d_in, const int* in_sizes, int n_in,
                              void* d_out, int out_size) {
    const float* X  = (const float*)d_in[0];
    const float* W0 = (const float*)d_in[1];
    const float* W1 = (const float*)d_in[2];
    const float* W2 = (const float*)d_in[3];
    float* out = (float*)d_out;

    cudaFuncSetAttribute(gemm_kernel,
                         cudaFuncAttributeMaxDynamicSharedMemorySize, SMEM_TOTAL);

    prep_kernel<<<(W_VEC4 + X_VEC4) / 256, 256>>>(X, W0, W1, W2);
    gemm_kernel<<<dim3(NTOT / BN, MTOT / BM), 256, SMEM_TOTAL>>>();
    prefix_kernel<<<(BATCH * HIDDEN) / 8, 256>>>();
    finalize_kernel<<<dim3(BATCH, NCH), 256>>>(out);
}

// round 12
// speedup vs baseline: 1.0968x; 1.0018x over previous
#include <cuda_runtime.h>
#include <cuda_fp16.h>
#include <cstdint>

// ---------------------------------------------------------------------------
// Problem constants
// ---------------------------------------------------------------------------
#define BATCH   4
#define SEQ     4096
#define HIDDEN  1024
#define MTOT    (BATCH * SEQ)          // 16384
#define NTOT    (3 * HIDDEN)           // 3072 (S | out1 | out2)

// GEMM tiling: CTA 128x128, 8 warps of 64x32, BK=64 (R7 optimum config)
#define BM 128
#define BN 128
#define BK 64                           // 64 fp16 = 128 B row (SW128 swizzle)
#define NKT (HIDDEN / BK)               // 16 k-tiles

#define TILE_BYTES  16384               // 128 x 64 fp16
#define STAGE_BYTES (2 * TILE_BYTES)    // A + B = 32 KB
#define NSTAGE 3
#define SMEM_TOTAL  (NSTAGE * STAGE_BYTES)   // 96 KB, 2 CTAs/SM

// Scan tiling: 32-row chunks
#define NCH   128
#define CHUNK 32

// Prep sizes (vec4 units)
#define W_VEC4 ((NTOT * HIDDEN) / 4)                  // 786432
#define X_VEC4 ((int)(((size_t)MTOT * HIDDEN) / 4))   // 4194304

// ---------------------------------------------------------------------------
// Scratch (static device memory only; no allocations allowed)
// ---------------------------------------------------------------------------
__device__ __align__(256) __half         g_Yh[(size_t)MTOT * NTOT];       // 96 MB
__device__ __align__(256) unsigned short g_Xh[(size_t)MTOT * HIDDEN];     // 32 MB
__device__ __align__(256) unsigned short g_Wh[(size_t)NTOT * HIDDEN];     // 6 MB
__device__ __align__(256) float          g_cmax[(size_t)BATCH * HIDDEN * NCH]; // 2 MB

// ---------------------------------------------------------------------------
// Small helpers
// ---------------------------------------------------------------------------
__device__ __forceinline__ uint32_t smem_to_u32(const void* smem_ptr) {
    uint32_t addr;
    asm("{ .reg .u64 tmp; cvta.to.shared.u64 tmp, %1; cvt.u32.u64 %0, tmp; }"
        : "=r"(addr) : "l"(smem_ptr));
    return addr;
}

__device__ __forceinline__ void cp_async16(uint32_t saddr, const void* gaddr) {
    asm volatile("cp.async.cg.shared.global [%0], [%1], 16;"
                 :: "r"(saddr), "l"(gaddr));
}
__device__ __forceinline__ void cp_commit() {
    asm volatile("cp.async.commit_group;");
}
template <int N>
__device__ __forceinline__ void cp_wait() {
    asm volatile("cp.async.wait_group %0;" :: "n"(N));
}

__device__ __forceinline__ void ldmatrix_x4(uint32_t& r0, uint32_t& r1,
                                            uint32_t& r2, uint32_t& r3,
                                            uint32_t addr) {
    asm volatile("ldmatrix.sync.aligned.m8n8.x4.shared.b16 {%0,%1,%2,%3}, [%4];"
                 : "=r"(r0), "=r"(r1), "=r"(r2), "=r"(r3) : "r"(addr));
}

__device__ __forceinline__ void mma_f16(float* d, const uint32_t* a,
                                        const uint32_t* b) {
    asm volatile(
        "mma.sync.aligned.m16n8k16.row.col.f32.f16.f16.f32 "
        "{%0,%1,%2,%3}, {%4,%5,%6,%7}, {%8,%9}, {%0,%1,%2,%3};"
        : "+f"(d[0]), "+f"(d[1]), "+f"(d[2]), "+f"(d[3])
        : "r"(a[0]), "r"(a[1]), "r"(a[2]), "r"(a[3]), "r"(b[0]), "r"(b[1]));
}

#define NEG_INF __int_as_float(0xff800000)

// ---------------------------------------------------------------------------
// Merged prep: blocks [0, W_VEC4/256) convert Wcat; the rest convert X.
// Wcat = [(W0+W1)/8 ; W1 ; W2], all fp16.
// ---------------------------------------------------------------------------
__global__ __launch_bounds__(256) void prep_kernel(const float* __restrict__ X,
                                                   const float* __restrict__ W0,
                                                   const float* __restrict__ W1,
                                                   const float* __restrict__ W2) {
    size_t gi = (size_t)blockIdx.x * blockDim.x + threadIdx.x;
    if (gi < W_VEC4) {
        size_t e = gi * 4;
        int n = (int)(e >> 10);
        float4 w;
        if (n < HIDDEN) {
            float4 a = *reinterpret_cast<const float4*>(W0 + e);
            float4 b = *reinterpret_cast<const float4*>(W1 + e);
            w = make_float4((a.x + b.x) * 0.125f, (a.y + b.y) * 0.125f,
                            (a.z + b.z) * 0.125f, (a.w + b.w) * 0.125f);
        } else if (n < 2 * HIDDEN) {
            w = *reinterpret_cast<const float4*>(W1 + (e - (size_t)HIDDEN * HIDDEN));
        } else {
            w = *reinterpret_cast<const float4*>(W2 + (e - (size_t)2 * HIDDEN * HIDDEN));
        }
        ushort4 h;
        h.x = __half_as_ushort(__float2half_rn(w.x));
        h.y = __half_as_ushort(__float2half_rn(w.y));
        h.z = __half_as_ushort(__float2half_rn(w.z));
        h.w = __half_as_ushort(__float2half_rn(w.w));
        reinterpret_cast<ushort4*>(g_Wh)[gi] = h;
    } else {
        size_t i = gi - W_VEC4;
        float4 v = reinterpret_cast<const float4*>(X)[i];
        ushort4 h;
        h.x = __half_as_ushort(__float2half_rn(v.x));
        h.y = __half_as_ushort(__float2half_rn(v.y));
        h.z = __half_as_ushort(__float2half_rn(v.z));
        h.w = __half_as_ushort(__float2half_rn(v.w));
        reinterpret_cast<ushort4*>(g_Xh)[i] = h;
    }
}

// ---------------------------------------------------------------------------
// GEMM: Yh[16384,3072] = fp16( Xh@Wh^T ); fused per-chunk max of S columns.
// CTA 128x128, 8 warps of 64x32, 3-stage cp.async pipeline, 2 CTAs/SM.
// (R7 ordering: wait -> sync -> prefetch -> compute.)
// ---------------------------------------------------------------------------
__device__ __forceinline__ void load_stage(uint32_t sbuf, int kt,
                                           int m0, int n0, int tid) {
    const int k0 = kt << 6;
#pragma unroll
    for (int i = 0; i < 4; i++) {
        int id  = tid + i * 256;
        int row = id >> 3;
        int c   = id & 7;
        uint32_t off = (uint32_t)(row << 7) | (uint32_t)((c ^ (row & 7)) << 4);
        cp_async16(sbuf + off,
                   g_Xh + ((size_t)(m0 + row) << 10) + k0 + c * 8);
        cp_async16(sbuf + TILE_BYTES + off,
                   g_Wh + ((size_t)(n0 + row) << 10) + k0 + c * 8);
    }
    cp_commit();
}

__global__ __launch_bounds__(256, 2) void gemm_kernel() {
    extern __shared__ char smem[];
    const uint32_t smem_base = smem_to_u32(smem);
    const int tid = threadIdx.x;
    const int wid = tid >> 5;
    const int lid = tid & 31;
    const int n0 = blockIdx.x * BN;
    const int m0 = blockIdx.y * BM;

    // Warp layout: 2 (m) x 4 (n); warp tile 64 x 32
    const int wm = (wid & 1) * 64;
    const int wn = (wid >> 1) * 32;

    // ldmatrix lane geometry
    const int lrow = (lid & 7) + ((lid >> 3) & 1) * 8;   // row within 16-row tile
    const int lchk = (lid >> 4);                          // 0/1: k 16B chunk

    float acc[4][4][4];
#pragma unroll
    for (int mt = 0; mt < 4; mt++)
#pragma unroll
        for (int nt = 0; nt < 4; nt++)
#pragma unroll
            for (int j = 0; j < 4; j++) acc[mt][nt][j] = 0.0f;

    load_stage(smem_base, 0, m0, n0, tid);
    load_stage(smem_base + STAGE_BYTES, 1, m0, n0, tid);

#pragma unroll 1
    for (int kt = 0; kt < NKT; kt++) {
        if (kt == NKT - 1) cp_wait<0>();
        else               cp_wait<1>();
        __syncthreads();
        // Prefetch kt+2: its buffer was last read in iteration kt-1, which
        // every warp finished before the barrier above.
        if (kt + 2 < NKT) {
            uint32_t sb = smem_base + ((kt + 2) % NSTAGE) * STAGE_BYTES;
            load_stage(sb, kt + 2, m0, n0, tid);
        }

        const uint32_t sA = smem_base + (kt % NSTAGE) * STAGE_BYTES;
        const uint32_t sB = sA + TILE_BYTES;

#pragma unroll
        for (int s = 0; s < 4; s++) {        // 4 sub-steps of k16
            const int chunk = 2 * s + lchk;
            // B fragments: 4 n-tiles of 8 rows
            uint32_t b[4][2];
#pragma unroll
            for (int np = 0; np < 2; np++) {
                int row = wn + np * 16 + lrow;
                uint32_t addr = sB + (uint32_t)(row << 7)
                              + (uint32_t)((chunk ^ (row & 7)) << 4);
                uint32_t r0, r1, r2, r3;
                ldmatrix_x4(r0, r1, r2, r3, addr);
                b[2 * np][0] = r0;     b[2 * np][1] = r2;
                b[2 * np + 1][0] = r1; b[2 * np + 1][1] = r3;
            }
            // A fragments: 4 m-tiles of 16 rows
            uint32_t a[4][4];
#pragma unroll
            for (int mt = 0; mt < 4; mt++) {
                int row = wm + mt * 16 + lrow;
                uint32_t addr = sA + (uint32_t)(row << 7)
                              + (uint32_t)((chunk ^ (row & 7)) << 4);
                ldmatrix_x4(a[mt][0], a[mt][1], a[mt][2], a[mt][3], addr);
            }
#pragma unroll
            for (int mt = 0; mt < 4; mt++)
#pragma unroll
                for (int nt = 0; nt < 4; nt++)
                    mma_f16(acc[mt][nt], a[mt], b[nt]);
        }
    }

    // Fused chunk-max for S columns (n0 < HIDDEN): warp tile covers two
    // 32-row chunks (mt 0,1 -> rows 0..31; mt 2,3 -> rows 32..63).
    if (n0 < HIDDEN) {
        const int b_idx  = m0 >> 12;                       // batch
        const int chbase = ((m0 & 4095) >> 5) + (wm >> 5); // 32-row chunk idx
#pragma unroll
        for (int half = 0; half < 2; half++) {
#pragma unroll
            for (int nt = 0; nt < 4; nt++) {
                float v0 = NEG_INF, v1 = NEG_INF;
#pragma unroll
                for (int mt = 2 * half; mt < 2 * half + 2; mt++) {
                    v0 = fmaxf(v0, fmaxf(acc[mt][nt][0], acc[mt][nt][2]));
                    v1 = fmaxf(v1, fmaxf(acc[mt][nt][1], acc[mt][nt][3]));
                }
#pragma unroll
                for (int msk = 4; msk <= 16; msk <<= 1) {
                    v0 = fmaxf(v0, __shfl_xor_sync(0xffffffffu, v0, msk));
                    v1 = fmaxf(v1, __shfl_xor_sync(0xffffffffu, v1, msk));
                }
                if (lid < 4) {
                    int col = n0 + wn + nt * 8 + lid * 2;
                    int ch  = chbase + half;
                    g_cmax[((size_t)(b_idx * HIDDEN + col)) * NCH + ch]     = v0;
                    g_cmax[((size_t)(b_idx * HIDDEN + col + 1)) * NCH + ch] = v1;
                }
            }
        }
    }

    // Epilogue: fp16 stores to g_Yh
    const int r0l = lid >> 2;          // 0..7
    const int c0l = (lid & 3) * 2;     // 0,2,4,6
#pragma unroll
    for (int mt = 0; mt < 4; mt++) {
#pragma unroll
        for (int nt = 0; nt < 4; nt++) {
            size_t row = (size_t)(m0 + wm + mt * 16 + r0l);
            size_t col = (size_t)(n0 + wn + nt * 8 + c0l);
            __half2 h0 = __floats2half2_rn(acc[mt][nt][0], acc[mt][nt][1]);
            __half2 h1 = __floats2half2_rn(acc[mt][nt][2], acc[mt][nt][3]);
            *reinterpret_cast<__half2*>(g_Yh + row * NTOT + col) = h0;
            *reinterpret_cast<__half2*>(g_Yh + (row + 8) * NTOT + col) = h1;
        }
    }
}

// ---------------------------------------------------------------------------
// Prefix kernel: convert g_cmax rows (length 128) into EXCLUSIVE prefix
// maxes in-place. One WARP per row; float4 + shfl_up scan. Exact (max assoc).
// ---------------------------------------------------------------------------
__global__ __launch_bounds__(256) void prefix_kernel() {
    const int lane = threadIdx.x & 31;
    const int wrp  = threadIdx.x >> 5;
    float* row = g_cmax + ((size_t)blockIdx.x * 8 + wrp) * NCH;
    float4 v = reinterpret_cast<float4*>(row)[lane];
    float t = fmaxf(fmaxf(v.x, v.y), fmaxf(v.z, v.w));
#pragma unroll
    for (int off = 1; off < 32; off <<= 1) {
        float u = __shfl_up_sync(0xffffffffu, t, off);
        if (lane >= off) t = fmaxf(t, u);
    }
    float excl = __shfl_up_sync(0xffffffffu, t, 1);
    if (lane == 0) excl = NEG_INF;
    float4 e;
    e.x = excl;
    e.y = fmaxf(excl, v.x);
    e.z = fmaxf(e.y, v.y);
    e.w = fmaxf(e.z, v.z);
    reinterpret_cast<float4*>(row)[lane] = e;
}

// ---------------------------------------------------------------------------
// Finalize: run = prefix[ch]; in-chunk (32-row) cummax + epilogue
// out = (cm + out2) * cm + out1
// Grid (4, 128, 2), block 128; each thread does 4 channels (uint2 loads).
// z splits the 1024 channels into two 512-channel halves -> 1024 blocks.
// ---------------------------------------------------------------------------
__global__ __launch_bounds__(128) void finalize_kernel(float* __restrict__ out) {
    const int c  = (blockIdx.z * 128 + threadIdx.x) * 4;
    const int b  = blockIdx.x;
    const int ch = blockIdx.y;
    float run[4];
#pragma unroll
    for (int j = 0; j < 4; j++)
        run[j] = g_cmax[((size_t)(b * HIDDEN + c + j)) * NCH + ch];
    const size_t row0 = (size_t)b * SEQ + (size_t)ch * CHUNK;
#pragma unroll 2
    for (int s = 0; s < CHUNK; s++) {
        const size_t row = row0 + s;
        const size_t yb  = row * NTOT;
        uint2 svu = *reinterpret_cast<const uint2*>(g_Yh + yb + c);
        uint2 o1u = *reinterpret_cast<const uint2*>(g_Yh + yb + HIDDEN + c);
        uint2 o2u = *reinterpret_cast<const uint2*>(g_Yh + yb + 2 * HIDDEN + c);
        float2 sv01 = __half22float2(*reinterpret_cast<__half2*>(&svu.x));
        float2 sv23 = __half22float2(*reinterpret_cast<__half2*>(&svu.y));
        float2 o101 = __half22float2(*reinterpret_cast<__half2*>(&o1u.x));
        float2 o123 = __half22float2(*reinterpret_cast<__half2*>(&o1u.y));
        float2 o201 = __half22float2(*reinterpret_cast<__half2*>(&o2u.x));
        float2 o223 = __half22float2(*reinterpret_cast<__half2*>(&o2u.y));
        run[0] = fmaxf(run[0], sv01.x);
        run[1] = fmaxf(run[1], sv01.y);
        run[2] = fmaxf(run[2], sv23.x);
        run[3] = fmaxf(run[3], sv23.y);
        float4 r;
        r.x = (run[0] + o201.x) * run[0] + o101.x;
        r.y = (run[1] + o201.y) * run[1] + o101.y;
        r.z = (run[2] + o223.x) * run[2] + o123.x;
        r.w = (run[3] + o223.y) * run[3] + o123.y;
        *reinterpret_cast<float4*>(out + row * HIDDEN + c) = r;
    }
}

// ---------------------------------------------------------------------------
// Launch
// ---------------------------------------------------------------------------
extern "C" void kernel_launch(void* const* d_in, const int* in_sizes, int n_in,
                              void* d_out, int out_size) {
    const float* X  = (const float*)d_in[0];
    const float* W0 = (const float*)d_in[1];
    const float* W1 = (const float*)d_in[2];
    const float* W2 = (const float*)d_in[3];
    float* out = (float*)d_out;

    cudaFuncSetAttribute(gemm_kernel,
                         cudaFuncAttributeMaxDynamicSharedMemorySize, SMEM_TOTAL);

    prep_kernel<<<(W_VEC4 + X_VEC4) / 256, 256>>>(X, W0, W1, W2);
    gemm_kernel<<<dim3(NTOT / BN, MTOT / BM), 256, SMEM_TOTAL>>>();
    prefix_kernel<<<(BATCH * HIDDEN) / 8, 256>>>();
    finalize_kernel<<<dim3(BATCH, NCH, 2), 128>>>(out);
}